// round 13
// baseline (speedup 1.0000x reference)
#include <cuda_runtime.h>
#include <cuda_fp16.h>

#define NN 4096

typedef unsigned long long u64;

// fp16 complex scratch for the stage-8 intermediate (67 MB).
__device__ __half2 g_scr[(size_t)NN * NN];

// ---- packed f32x2 helpers (sm_103a FFMA2 path, PTX-only) ----
static __device__ __forceinline__ u64 pk2(float lo, float hi) {
    u64 r; asm("mov.b64 %0, {%1, %2};" : "=l"(r) : "f"(lo), "f"(hi)); return r;
}
static __device__ __forceinline__ void unpk2(u64 v, float& lo, float& hi) {
    asm("mov.b64 {%0, %1}, %2;" : "=f"(lo), "=f"(hi) : "l"(v));
}
static __device__ __forceinline__ u64 mul2(u64 a, u64 b) {
    u64 d; asm("mul.rn.f32x2 %0, %1, %2;" : "=l"(d) : "l"(a), "l"(b)); return d;
}
static __device__ __forceinline__ u64 fma2(u64 a, u64 b, u64 c) {
    u64 d; asm("fma.rn.f32x2 %0, %1, %2, %3;" : "=l"(d) : "l"(a), "l"(b), "l"(c)); return d;
}

// Packed twiddle: cs2/sn2 and negated copies (for the sub-side of butterflies).
struct Tw2 { u64 cs, sn, mcs, msn; };

// Build packed twiddle for index k and packed weights w2 = (W[k,d0], W[k,d0+1]).
// Scalar rounding order matches the reference: ((-2pi)*(k/4096)) * w.
static __device__ __forceinline__ Tw2 make_tw2(int k, u64 w2) {
    const float fc = (-6.2831855f) * ((float)k * (1.0f / 4096.0f));
    u64 ph2 = mul2(pk2(fc, fc), w2);
    float p0, p1; unpk2(ph2, p0, p1);
    float s0, c0, s1, c1;
    __sincosf(p0, &s0, &c0);
    __sincosf(p1, &s1, &c1);
    Tw2 t;
    t.cs = pk2(c0, c1);
    t.sn = pk2(s0, s1);
    const u64 m1 = pk2(-1.0f, -1.0f);
    t.mcs = mul2(t.cs, m1);
    t.msn = mul2(t.sn, m1);
    return t;
}

// Packed butterfly on (top, bot) complex pairs (2 columns per op):
//   top' = top + tw*bot ; bot' = top - tw*bot, tw = cs + i*sn.
//   top_r' = cs*br + (msn*bi + tr)     bot_r' = mcs*br + (sn*bi + tr)
//   top_i' = cs*bi + ( sn*br + ti)     bot_i' = mcs*bi + (msn*br + ti)
static __device__ __forceinline__ void bf2(u64& tr, u64& ti, u64& br, u64& bi,
                                           const Tw2& t) {
    const u64 ntr = fma2(t.cs,  br, fma2(t.msn, bi, tr));
    const u64 nti = fma2(t.cs,  bi, fma2(t.sn,  br, ti));
    const u64 nbr = fma2(t.mcs, br, fma2(t.sn,  bi, tr));
    const u64 nbi = fma2(t.mcs, bi, fma2(t.msn, br, ti));
    tr = ntr; ti = nti; br = nbr; bi = nbi;
}

// ---------------------------------------------------------------------------
// Kernel A (2 cols/thread, f32x2 math): permutation + stages step=2..256.
// CTA = 256-row group x 16-column tile, 128 threads: m = tx>>3, cp = tx&7,
// thread owns columns d0 = 2*cp, d0+1 packed in 64-bit registers.
// ---------------------------------------------------------------------------
__global__ __launch_bounds__(128) void fftA(const float* __restrict__ x,
                                            const float* __restrict__ W) {
    __shared__ ulonglong2 sm[256 * 8];  // 32 KB: {re_pack, im_pack} per (row,cp)
    const int tx = threadIdx.x;
    const int m  = tx >> 3;           // 0..15
    const int cp = tx & 7;            // 0..7
    const int d0 = blockIdx.x * 16 + 2 * cp;
    const int g  = blockIdx.y;        // 0..15
    const int gin = g ^ 8;            // i^2048 flips group bit 3

    u64 re[16], im[16];
    const u64 zero2 = pk2(0.0f, 0.0f);

    // Load 16 rows x 2 cols: the 8B global load IS the packed (re0,re1).
    {
        const float* xp = x + (size_t)(gin * 256 + m * 16) * NN + d0;
        #pragma unroll
        for (int i = 0; i < 16; ++i) {
            re[i] = *reinterpret_cast<const u64*>(xp + (size_t)i * NN);
            im[i] = zero2;
        }
    }

    // Stages step = 2,4,8,16 : local row l = m*16+i, r = i mod step.
    #pragma unroll
    for (int s = 1; s <= 4; ++s) {
        const int step = 1 << s, half = step >> 1;
        #pragma unroll
        for (int r = 0; r < half; ++r) {
            const int k = r << (12 - s);
            const u64 w2 = *reinterpret_cast<const u64*>(W + (size_t)k * NN + d0);
            const Tw2 t = make_tw2(k, w2);
            #pragma unroll
            for (int bb = 0; bb < 16; bb += step) {
                const int j = bb + r;
                bf2(re[j], im[j], re[j + half], im[j + half], t);
            }
        }
    }

    // Exchange: write rows m*16+i, read rows m+16j (16B accesses).
    #pragma unroll
    for (int i = 0; i < 16; ++i)
        sm[(m * 16 + i) * 8 + cp] = make_ulonglong2(re[i], im[i]);
    __syncthreads();
    #pragma unroll
    for (int j = 0; j < 16; ++j) {
        ulonglong2 v = sm[(m + 16 * j) * 8 + cp];
        re[j] = v.x;
        im[j] = v.y;
    }

    // Stages step = 32,64,128,256 : local row l = m + 16j.
    #pragma unroll
    for (int s = 5; s <= 8; ++s) {
        const int jstep = 1 << (s - 4), jhalf = jstep >> 1;
        #pragma unroll
        for (int rr = 0; rr < jhalf; ++rr) {
            const int k = (m + 16 * rr) << (12 - s);
            const u64 w2 = *reinterpret_cast<const u64*>(W + (size_t)k * NN + d0);
            const Tw2 t = make_tw2(k, w2);
            #pragma unroll
            for (int jb = 0; jb < 16; jb += jstep) {
                const int j = jb + rr;
                bf2(re[j], im[j], re[j + jhalf], im[j + jhalf], t);
            }
        }
    }

    // Store rows g*256 + m + 16j: two half2 packed into one uint2 (8B).
    {
        const size_t base = (size_t)(g * 256 + m) * NN + d0;
        #pragma unroll
        for (int j = 0; j < 16; ++j) {
            const size_t idx = base + (size_t)(16 * j) * NN;
            float r0, r1, i0, i1;
            unpk2(re[j], r0, r1);
            unpk2(im[j], i0, i1);
            union { __half2 h[2]; uint2 u; } pk;
            pk.h[0] = __floats2half2_rn(r0, i0);
            pk.h[1] = __floats2half2_rn(r1, i1);
            *reinterpret_cast<uint2*>(g_scr + idx) = pk.u;
        }
    }
}

// ---------------------------------------------------------------------------
// Kernel B (2 cols/thread, f32x2 math): stages step = 512..4096.
// Row i = a*256 + b; 16-point network over a for fixed b.
// d0 = blockIdx.x*512 + 2*tx. Out store: re[a] pack IS the float2 to emit.
// ---------------------------------------------------------------------------
__global__ __launch_bounds__(256) void fftB(const float* __restrict__ W,
                                            float* __restrict__ out) {
    const int d0 = blockIdx.x * 512 + 2 * threadIdx.x; // grid.x = 8
    const int b  = blockIdx.y;                         // 0..255

    u64 re[16], im[16];
    {
        const size_t base = (size_t)b * NN + d0;
        #pragma unroll
        for (int a = 0; a < 16; ++a) {
            const size_t idx = base + (size_t)(a * 256) * NN;
            union { uint2 u; __half2 h[2]; } pk;
            pk.u = *reinterpret_cast<const uint2*>(g_scr + idx);
            float2 v0 = __half22float2(pk.h[0]);   // (re0, im0)
            float2 v1 = __half22float2(pk.h[1]);   // (re1, im1)
            re[a] = pk2(v0.x, v1.x);
            im[a] = pk2(v0.y, v1.y);
        }
    }

    #pragma unroll
    for (int s = 9; s <= 12; ++s) {
        const int astep = 1 << (s - 8), ahalf = astep >> 1;
        #pragma unroll
        for (int rr = 0; rr < ahalf; ++rr) {
            const int k = (256 * rr + b) << (12 - s);
            const u64 w2 = *reinterpret_cast<const u64*>(W + (size_t)k * NN + d0);
            const Tw2 t = make_tw2(k, w2);
            #pragma unroll
            for (int ab = 0; ab < 16; ab += astep) {
                const int a = ab + rr;
                bf2(re[a], im[a], re[a + ahalf], im[a + ahalf], t);
            }
        }
    }

    // Emit real parts: re[a] already holds (re0,re1) = the 8B to store.
    {
        const size_t base = (size_t)b * NN + d0;
        #pragma unroll
        for (int a = 0; a < 16; ++a)
            *reinterpret_cast<u64*>(out + base + (size_t)(a * 256) * NN) = re[a];
    }
}

extern "C" void kernel_launch(void* const* d_in, const int* in_sizes, int n_in,
                              void* d_out, int out_size) {
    if (n_in < 2 || d_in == nullptr || d_out == nullptr || in_sizes == nullptr)
        return;
    if (d_in[0] == nullptr || d_in[1] == nullptr)
        return;
    if (in_sizes[0] < NN * NN || in_sizes[1] < NN * NN)
        return;
    if (out_size < NN * NN)
        return;

    const float* x = (const float*)d_in[0]; // (4096,4096) float32
    const float* W = (const float*)d_in[1]; // (4096,4096) float32 weights
    float* out = (float*)d_out;             // (4096,4096) float32 = Re(FFT)

    dim3 gA(NN / 16, 16);   // 256 column tiles x 16 row groups, 128 thr
    fftA<<<gA, 128>>>(x, W);

    dim3 gB(NN / 512, 256); // 8 column tiles x 256 b-values, 256 thr
    fftB<<<gB, 256>>>(W, out);
}

// round 14
// speedup vs baseline: 1.0650x; 1.0650x over previous
#include <cuda_runtime.h>
#include <cuda_fp16.h>

#define NN 4096

// fp16 complex scratch for the stage-8 intermediate (67 MB).
__device__ __half2 g_scr[(size_t)NN * NN];

// butterfly: (top, bot) -> (top + tw*bot, top - tw*bot), tw = cs + i*sn
static __device__ __forceinline__ void bf(float& tr_, float& ti_,
                                          float& br_, float& bi_,
                                          float cs, float sn) {
    float tr = cs * br_ - sn * bi_;
    float ti = cs * bi_ + sn * br_;
    br_ = tr_ - tr;
    bi_ = ti_ - ti;
    tr_ += tr;
    ti_ += ti;
}

// twiddle-free butterfly (r = 0 -> tw = 1 - 0i -> temp = bot, bit-identical
// to the general path at k = 0): (top, bot) -> (top + bot, top - bot)
static __device__ __forceinline__ void bf0(float& tr_, float& ti_,
                                           float& br_, float& bi_) {
    const float tr = br_, ti = bi_;
    br_ = tr_ - tr;
    bi_ = ti_ - ti;
    tr_ += tr;
    ti_ += ti;
}

// phase = (-2*pi) * (k/4096) * W[k,d], fp32, reference rounding order
static __device__ __forceinline__ float phase_of(int k, float w) {
    return (-6.2831855f) * ((float)k * (1.0f / 4096.0f)) * w;
}

// ---------------------------------------------------------------------------
// Kernel A (R8 base + r=0 specialization): permutation + stages step=2..256.
// CTA = 256-row group x 16-column tile, 256 threads (m = tx>>4, c = tx&15).
// Round 1 (stages 2..16): r=0 butterflies (15 of 32/thread) are pure add/sub,
// skipping 4 sincos + 4 W-loads per thread. Round 2 unchanged (r=0 only for
// the m=0 slot -> divergent, not worth specializing).
// ---------------------------------------------------------------------------
__global__ __launch_bounds__(256) void fftA(const float* __restrict__ x,
                                            const float* __restrict__ W) {
    __shared__ float2 sm[256 * 16];   // 32 KB exchange
    const int tx = threadIdx.x;
    const int m  = tx >> 4;           // 0..15
    const int c  = tx & 15;           // 0..15
    const int d  = blockIdx.x * 16 + c;
    const int g  = blockIdx.y;        // 0..15
    const int gin = g ^ 8;            // i^2048 flips group bit 3

    float re[16], im[16];

    // Load 16 contiguous rows of column d from the permuted source group.
    {
        const float* xp = x + (size_t)(gin * 256 + m * 16) * NN + d;
        #pragma unroll
        for (int i = 0; i < 16; ++i) {
            re[i] = xp[(size_t)i * NN];
            im[i] = 0.0f;
        }
    }

    // Round 1: stages step = 2,4,8,16 (local row l = m*16+i, r = i mod step).
    // r = 0 path: twiddle-free add/sub.
    #pragma unroll
    for (int s = 1; s <= 4; ++s) {
        const int step = 1 << s, half = step >> 1;
        // r = 0: no twiddle, no W-load, no sincos.
        #pragma unroll
        for (int bb = 0; bb < 16; bb += step)
            bf0(re[bb], im[bb], re[bb + half], im[bb + half]);
        // r = 1 .. half-1: general path.
        #pragma unroll
        for (int r = 1; r < half; ++r) {
            const int k = r << (12 - s);
            float sn, cs;
            __sincosf(phase_of(k, W[(size_t)k * NN + d]), &sn, &cs);
            #pragma unroll
            for (int bb = 0; bb < 16; bb += step) {
                const int j = bb + r;
                bf(re[j], im[j], re[j + half], im[j + half], cs, sn);
            }
        }
    }

    // Exchange: write rows m*16+i, read rows m+16j.
    #pragma unroll
    for (int i = 0; i < 16; ++i)
        sm[(m * 16 + i) * 16 + c] = make_float2(re[i], im[i]);
    __syncthreads();
    #pragma unroll
    for (int j = 0; j < 16; ++j) {
        float2 v = sm[(m + 16 * j) * 16 + c];
        re[j] = v.x;
        im[j] = v.y;
    }

    // Round 2: stages step = 32,64,128,256 (local row l = m + 16j).
    #pragma unroll
    for (int s = 5; s <= 8; ++s) {
        const int jstep = 1 << (s - 4), jhalf = jstep >> 1;
        #pragma unroll
        for (int rr = 0; rr < jhalf; ++rr) {
            const int k = (m + 16 * rr) << (12 - s);
            float sn, cs;
            __sincosf(phase_of(k, W[(size_t)k * NN + d]), &sn, &cs);
            #pragma unroll
            for (int jb = 0; jb < 16; jb += jstep) {
                const int j = jb + rr;
                bf(re[j], im[j], re[j + jhalf], im[j + jhalf], cs, sn);
            }
        }
    }

    // Store rows g*256 + m + 16j as packed half2.
    {
        __half2* sp = g_scr + (size_t)(g * 256 + m) * NN + d;
        #pragma unroll
        for (int j = 0; j < 16; ++j)
            sp[(size_t)(16 * j) * NN] = __floats2half2_rn(re[j], im[j]);
    }
}

// ---------------------------------------------------------------------------
// Kernel B (R8 form, unchanged): stages step = 512..4096. Row i = a*256 + b;
// 16-point network over a for fixed b. Reads fp16 scratch; writes real part.
// ---------------------------------------------------------------------------
__global__ __launch_bounds__(256) void fftB(const float* __restrict__ W,
                                            float* __restrict__ out) {
    const int d = blockIdx.x * 256 + threadIdx.x;  // grid.x = 16
    const int b = blockIdx.y;                      // 0..255

    float re[16], im[16];
    {
        const __half2* sp = g_scr + (size_t)b * NN + d;
        #pragma unroll
        for (int a = 0; a < 16; ++a) {
            float2 v = __half22float2(sp[(size_t)(a * 256) * NN]);
            re[a] = v.x;
            im[a] = v.y;
        }
    }

    #pragma unroll
    for (int s = 9; s <= 12; ++s) {
        const int astep = 1 << (s - 8), ahalf = astep >> 1;
        #pragma unroll
        for (int rr = 0; rr < ahalf; ++rr) {
            const int k = (256 * rr + b) << (12 - s);
            float sn, cs;
            __sincosf(phase_of(k, W[(size_t)k * NN + d]), &sn, &cs);
            #pragma unroll
            for (int ab = 0; ab < 16; ab += astep) {
                const int a = ab + rr;
                bf(re[a], im[a], re[a + ahalf], im[a + ahalf], cs, sn);
            }
        }
    }

    {
        float* op = out + (size_t)b * NN + d;
        #pragma unroll
        for (int a = 0; a < 16; ++a)
            op[(size_t)(a * 256) * NN] = re[a];
    }
}

extern "C" void kernel_launch(void* const* d_in, const int* in_sizes, int n_in,
                              void* d_out, int out_size) {
    if (n_in < 2 || d_in == nullptr || d_out == nullptr || in_sizes == nullptr)
        return;
    if (d_in[0] == nullptr || d_in[1] == nullptr)
        return;
    if (in_sizes[0] < NN * NN || in_sizes[1] < NN * NN)
        return;
    if (out_size < NN * NN)
        return;

    const float* x = (const float*)d_in[0]; // (4096,4096) float32
    const float* W = (const float*)d_in[1]; // (4096,4096) float32 weights
    float* out = (float*)d_out;             // (4096,4096) float32 = Re(FFT)

    dim3 gA(NN / 16, 16);   // 256 column tiles x 16 row groups, 256 thr
    fftA<<<gA, 256>>>(x, W);

    dim3 gB(NN / 256, 256); // 16 column tiles x 256 b-values
    fftB<<<gB, 256>>>(W, out);
}